// round 14
// baseline (speedup 1.0000x reference)
#include <cuda_runtime.h>
#include <cstdint>
#include <math.h>

#define H    4096
#define NH   32
#define HD   128
#define FF   11008
#define SEQ  1024
#define NL   2
#define OUT  512

#define KB_H (H / 16)     // 256
#define KB_F (FF / 16)    // 688
#define MB_S (SEQ / 16)   // 64
#define SPLITK 4

// ---------------- scratch (static device globals; no runtime alloc) ----------
__device__ float g_h  [SEQ * H];
__device__ float g_qkv[SEQ * 3 * H];
__device__ float g_ao [SEQ * H];
__device__ float g_gu [SEQ * 2 * FF];
__device__ float g_rs [SEQ];
__device__ float g_part[SPLITK * SEQ * OUT];

// split activations (A-side), sized for the largest (K=FF)
__device__ uint4 g_a4[(size_t)2 * MB_S * KB_F * 32];

// split weights (B-side), fragment-major uint2 {r0,r1}
#define SWQ_L  ((size_t)2 * (H  / 8) * KB_H * 32)
#define SWGU_L ((size_t)2 * (2 * FF / 8) * KB_H * 32)
#define SWD_L  ((size_t)2 * (H  / 8) * KB_F * 32)
#define SWOUT  ((size_t)2 * (OUT/ 8) * KB_H * 32)
#define SQKV_L ((size_t)2 * (3 * H / 8) * KB_H * 32)
__device__ uint2 g_wqkv[NL * SQKV_L];
__device__ uint2 g_wo [NL * SWQ_L];
__device__ uint2 g_wgu[NL * SWGU_L];
__device__ uint2 g_wd [NL * SWD_L];
__device__ uint2 g_wout[SWOUT];

// ---------------- helpers ----------------------------------------------------
__device__ __forceinline__ uint32_t smem_u32(const void* p) {
    uint32_t a;
    asm("{ .reg .u64 t; cvta.to.shared.u64 t, %1; cvt.u32.u64 %0, t; }"
        : "=r"(a) : "l"(p));
    return a;
}
__device__ __forceinline__ void cp16(uint32_t dst, const void* src) {
    asm volatile("cp.async.cg.shared.global [%0], [%1], 16;"
                 :: "r"(dst), "l"(src));
}
// split (f0,f1) -> packed bf16x2 hi (low16 = f0) and lo (residuals)
__device__ __forceinline__ void split2(float2 f, uint32_t& hi, uint32_t& lo) {
    asm("cvt.rn.bf16x2.f32 %0, %1, %2;" : "=r"(hi) : "f"(f.y), "f"(f.x));
    float h0 = __uint_as_float(hi << 16);
    float h1 = __uint_as_float(hi & 0xffff0000u);
    float r0 = f.x - h0;
    float r1 = f.y - h1;
    asm("cvt.rn.bf16x2.f32 %0, %1, %2;" : "=r"(lo) : "f"(r1), "f"(r0));
}
__device__ __forceinline__ void mma_bf16(float* d, const uint32_t* a,
                                         const uint32_t* b) {
    asm volatile(
        "mma.sync.aligned.m16n8k16.row.col.f32.bf16.bf16.f32 "
        "{%0,%1,%2,%3}, {%4,%5,%6,%7}, {%8,%9}, {%0,%1,%2,%3};"
        : "+f"(d[0]), "+f"(d[1]), "+f"(d[2]), "+f"(d[3])
        : "r"(a[0]), "r"(a[1]), "r"(a[2]), "r"(a[3]),
          "r"(b[0]), "r"(b[1]));
}

// ---------------- shared fragment-writer (16x128 smem tile -> a4) ------------
__device__ __forceinline__ void write_frags(const float (*Xs)[132],
                                            uint4* __restrict__ dst,
                                            int mb, int kb0, int MB, int KB,
                                            int tid, int nthreads)
{
    for (int idx = tid; idx < 512; idx += nthreads) {
        int l = idx & 31, kbl = (idx >> 5) & 7, h = idx >> 8;
        int gid = l >> 2, tig = l & 3;
        int c0 = kbl * 16 + tig * 2;
        float2 p00 = make_float2(Xs[gid][c0],         Xs[gid][c0 + 1]);
        float2 p10 = make_float2(Xs[gid + 8][c0],     Xs[gid + 8][c0 + 1]);
        float2 p01 = make_float2(Xs[gid][c0 + 8],     Xs[gid][c0 + 9]);
        float2 p11 = make_float2(Xs[gid + 8][c0 + 8], Xs[gid + 8][c0 + 9]);
        uint32_t h00, l00, h10, l10, h01, l01, h11, l11;
        split2(p00, h00, l00); split2(p10, h10, l10);
        split2(p01, h01, l01); split2(p11, h11, l11);
        uint4 o = h ? make_uint4(l00, l10, l01, l11)
                    : make_uint4(h00, h10, h01, h11);
        dst[(((size_t)h * MB + mb) * KB + kb0 + kbl) * 32 + l] = o;
    }
}

// ---------------- rms scale: rs[row] = rsqrt(mean(x^2)+eps) ------------------
__global__ void __launch_bounds__(256)
rms_scale_kernel(const float* __restrict__ x, float* __restrict__ rs)
{
    int row = blockIdx.x;
    const float* xr = x + (size_t)row * H;
    float ss = 0.f;
    for (int i = threadIdx.x * 4; i < H; i += 1024) {
        float4 v = *(const float4*)(xr + i);
        ss += v.x * v.x + v.y * v.y + v.z * v.z + v.w * v.w;
    }
    __shared__ float red[8];
    #pragma unroll
    for (int o = 16; o > 0; o >>= 1) ss += __shfl_xor_sync(0xffffffffu, ss, o);
    if ((threadIdx.x & 31) == 0) red[threadIdx.x >> 5] = ss;
    __syncthreads();
    if (threadIdx.x == 0) {
        float tot = 0.f;
        #pragma unroll
        for (int i = 0; i < 8; i++) tot += red[i];
        rs[row] = rsqrtf(tot / (float)H + 1e-6f);
    }
}

// ---------------- convAS: split X[M][K] * rs[row] * w[col] -> a4 -------------
__global__ void __launch_bounds__(256)
convAS_kernel(const float* __restrict__ X, const float* __restrict__ rs,
              const float* __restrict__ w, uint4* __restrict__ dst,
              int M, int K)
{
    __shared__ float Xs[16][132];
    const int mb = blockIdx.x, kc = blockIdx.y;
    const int tid = threadIdx.x;
    #pragma unroll
    for (int it = 0; it < 2; it++) {
        int f4 = it * 256 + tid;
        int r = f4 >> 5, c4 = f4 & 31;
        float4 v = *(const float4*)(X + (size_t)(mb * 16 + r) * K + kc * 128 + c4 * 4);
        float sc = rs[mb * 16 + r];
        float4 wv = *(const float4*)(w + kc * 128 + c4 * 4);
        Xs[r][c4 * 4 + 0] = v.x * sc * wv.x;
        Xs[r][c4 * 4 + 1] = v.y * sc * wv.y;
        Xs[r][c4 * 4 + 2] = v.z * sc * wv.z;
        Xs[r][c4 * 4 + 3] = v.w * sc * wv.w;
    }
    __syncthreads();
    write_frags(Xs, dst, mb, kc * 8, M >> 4, K >> 4, tid, 256);
}

// ---------------- convA (plain): split X[M][K] -> a4 -------------------------
__global__ void __launch_bounds__(256)
convA_kernel(const float* __restrict__ X, uint4* __restrict__ dst, int M, int K)
{
    __shared__ float Xs[16][132];
    const int mb = blockIdx.x, kc = blockIdx.y;
    const int tid = threadIdx.x;
    #pragma unroll
    for (int it = 0; it < 2; it++) {
        int f4 = it * 256 + tid;
        int r = f4 >> 5, c4 = f4 & 31;
        float4 v = *(const float4*)(X + (size_t)(mb * 16 + r) * K + kc * 128 + c4 * 4);
        Xs[r][c4 * 4 + 0] = v.x; Xs[r][c4 * 4 + 1] = v.y;
        Xs[r][c4 * 4 + 2] = v.z; Xs[r][c4 * 4 + 3] = v.w;
    }
    __syncthreads();
    write_frags(Xs, dst, mb, kc * 8, M >> 4, K >> 4, tid, 256);
}

// ---------------- siluconv: a4 = split(silu(gu[:,k]) * gu[:,K+k]) ------------
__global__ void __launch_bounds__(256)
siluconv_kernel(const float* __restrict__ gu, uint4* __restrict__ dst,
                int M, int K)
{
    __shared__ float Xs[16][132];
    const int mb = blockIdx.x, kc = blockIdx.y;
    const int tid = threadIdx.x;
    #pragma unroll
    for (int it = 0; it < 2; it++) {
        int f4 = it * 256 + tid;
        int r = f4 >> 5, c4 = f4 & 31;
        const float* rowp = gu + (size_t)(mb * 16 + r) * 2 * K + kc * 128 + c4 * 4;
        float4 g = *(const float4*)(rowp);
        float4 u = *(const float4*)(rowp + K);
        Xs[r][c4 * 4 + 0] = g.x / (1.f + __expf(-g.x)) * u.x;
        Xs[r][c4 * 4 + 1] = g.y / (1.f + __expf(-g.y)) * u.y;
        Xs[r][c4 * 4 + 2] = g.z / (1.f + __expf(-g.z)) * u.z;
        Xs[r][c4 * 4 + 3] = g.w / (1.f + __expf(-g.w)) * u.w;
    }
    __syncthreads();
    write_frags(Xs, dst, mb, kc * 8, M >> 4, K >> 4, tid, 256);
}

// ---------------- convert B-side W[K][N] -> fragment-major uint2 -------------
__global__ void __launch_bounds__(256)
convB_kernel(const float* __restrict__ W, uint2* __restrict__ dst, int K, int N,
             int NB8d, int nc_off)
{
    __shared__ float Ws[16][132];
    const int kb = blockIdx.x, nc = blockIdx.y;
    const int tid = threadIdx.x;
    const int KB = K >> 4;
    #pragma unroll
    for (int it = 0; it < 2; it++) {
        int f4 = it * 256 + tid;
        int r = f4 >> 5, c4 = f4 & 31;
        float4 v = *(const float4*)(W + (size_t)(kb * 16 + r) * N + nc * 128 + c4 * 4);
        Ws[r][c4 * 4 + 0] = v.x; Ws[r][c4 * 4 + 1] = v.y;
        Ws[r][c4 * 4 + 2] = v.z; Ws[r][c4 * 4 + 3] = v.w;
    }
    __syncthreads();
    #pragma unroll
    for (int it = 0; it < 4; it++) {
        int idx = it * 256 + tid;
        int l = idx & 31, nbl = (idx >> 5) & 15, h = idx >> 9;
        int gid = l >> 2, tig = l & 3;
        int n = nbl * 8 + gid;
        float2 q0 = make_float2(Ws[2 * tig][n],     Ws[2 * tig + 1][n]);
        float2 q1 = make_float2(Ws[2 * tig + 8][n], Ws[2 * tig + 9][n]);
        uint32_t qh0, ql0, qh1, ql1;
        split2(q0, qh0, ql0); split2(q1, qh1, ql1);
        uint2 o = h ? make_uint2(ql0, ql1) : make_uint2(qh0, qh1);
        dst[(((size_t)h * NB8d + (nc_off + nc) * 16 + nbl) * KB + kb) * 32 + l] = o;
    }
}

// ---------------- convB_qkv: 3-in-1 (blockIdx.z selects Wq/Wk/Wv) ------------
__global__ void __launch_bounds__(256)
convB_qkv_kernel(const float* __restrict__ Wq, const float* __restrict__ Wk,
                 const float* __restrict__ Wv, uint2* __restrict__ dst)
{
    __shared__ float Ws[16][132];
    const int kb = blockIdx.x, nc = blockIdx.y, z = blockIdx.z;
    const int tid = threadIdx.x;
    const int KB = KB_H, NB8d = 3 * H / 8;
    const int nc_off = z * (H / 128);
    const float* W = (z == 0) ? Wq : (z == 1) ? Wk : Wv;
    #pragma unroll
    for (int it = 0; it < 2; it++) {
        int f4 = it * 256 + tid;
        int r = f4 >> 5, c4 = f4 & 31;
        float4 v = *(const float4*)(W + (size_t)(kb * 16 + r) * H + nc * 128 + c4 * 4);
        Ws[r][c4 * 4 + 0] = v.x; Ws[r][c4 * 4 + 1] = v.y;
        Ws[r][c4 * 4 + 2] = v.z; Ws[r][c4 * 4 + 3] = v.w;
    }
    __syncthreads();
    #pragma unroll
    for (int it = 0; it < 4; it++) {
        int idx = it * 256 + tid;
        int l = idx & 31, nbl = (idx >> 5) & 15, h = idx >> 9;
        int gid = l >> 2, tig = l & 3;
        int n = nbl * 8 + gid;
        float2 q0 = make_float2(Ws[2 * tig][n],     Ws[2 * tig + 1][n]);
        float2 q1 = make_float2(Ws[2 * tig + 8][n], Ws[2 * tig + 9][n]);
        uint32_t qh0, ql0, qh1, ql1;
        split2(q0, qh0, ql0); split2(q1, qh1, ql1);
        uint2 o = h ? make_uint2(ql0, ql1) : make_uint2(qh0, qh1);
        dst[(((size_t)h * NB8d + (nc_off + nc) * 16 + nbl) * KB + kb) * 32 + l] = o;
    }
}

// ---------------- split-bf16 tensor-core GEMM ---------------------------------
// B via 3-stage cp.async SMEM pipeline (16KB/stage); A fragments loaded
// DIRECTLY from GMEM/L2 (coalesced LDG.128 per lane) with 1-deep register
// prefetch over the im loop. KBs: KB stride; NCr: chunks per CTA;
// blockIdx.z = split-K partition (C offset z*M*N; Cin/bias null when used).
#define BUFB 16384
#define NST 3
#define GSM3 (NST * BUFB)
__global__ void __launch_bounds__(256, 2)
tgemm2_kernel(int M, int N, int KBs, int NCr,
              const uint4* __restrict__ A4, const uint2* __restrict__ B2,
              const float* __restrict__ Cin, const float* __restrict__ bias,
              float* __restrict__ C)
{
    extern __shared__ char smem[];
    const uint32_t sb = smem_u32(smem);
    const int tid = threadIdx.x;
    const int wid = tid >> 5, lane = tid & 31;
    const int wrow = wid >> 2, wcol = wid & 3;
    const int gid = lane >> 2, tig = lane & 3;
    const int bx = blockIdx.x, by = blockIdx.y;
    const int kz = blockIdx.z;

    const int KB = KBs;
    const size_t hA = (size_t)(M >> 4) * KB * 32;   // uint4 units
    const size_t hB = (size_t)(N >> 3) * KB * 32;   // uint2 units
    const int NC = NCr;
    const int kbz = kz * NCr * 2;
    C += (size_t)kz * M * N;

    auto issueB = [&](int c) {
        if (c < NC) {
            const int kb0 = kbz + c * 2;
            uint32_t dstB = sb + (uint32_t)(c % NST) * BUFB;
            #pragma unroll
            for (int it = 0; it < 4; it++) {
                int idx = it * 256 + tid;
                int inner = idx & 15, tile = idx >> 4;
                int kb = tile & 1, nb = (tile >> 1) & 15, h = tile >> 5;
                const uint2* src = B2 + (size_t)h * hB
                                 + ((size_t)(bx * 16 + nb) * KB + kb0 + kb) * 32 + inner * 2;
                cp16(dstB + idx * 16, src);
            }
        }
        asm volatile("cp.async.commit_group;" ::: "memory");
    };

    // A base for this thread's first row (mb = wrow*4), hi half
    const uint4* Abase = A4 + ((size_t)(by * 8 + wrow * 4) * KB) * 32 + lane;

    float acc[4][4][4];
    #pragma unroll
    for (int i = 0; i < 4; i++)
        #pragma unroll
        for (int j = 0; j < 4; j++)
            #pragma unroll
            for (int r = 0; r < 4; r++) acc[i][j][r] = 0.f;

    issueB(0);
    issueB(1);

    for (int c = 0; c < NC; c++) {
        asm volatile("cp.async.wait_group 1;" ::: "memory");
        __syncthreads();
        issueB(c + 2);

        const uint2* Bs2 = (const uint2*)(smem + (c % NST) * BUFB);
        const int kb0 = kbz + c * 2;

        #pragma unroll
        for (int ks = 0; ks < 2; ks++) {
            uint2 bh[4], bl[4];
            #pragma unroll
            for (int jn = 0; jn < 4; jn++) {
                int nb = wcol * 4 + jn;
                bh[jn] = Bs2[((0 * 16 + nb) * 2 + ks) * 32 + lane];
                bl[jn] = Bs2[((1 * 16 + nb) * 2 + ks) * 32 + lane];
            }
            // A direct from L2, register prefetch over im
            const uint4* ap = Abase + (size_t)(kb0 + ks) * 32;
            uint4 ah = ap[0];
            uint4 al = ap[hA];
            #pragma unroll
            for (int im = 0; im < 4; im++) {
                uint4 ahn, aln;
                if (im < 3) {
                    const uint4* apn = ap + (size_t)(im + 1) * KB * 32;
                    ahn = apn[0];
                    aln = apn[hA];
                }
                #pragma unroll
                for (int jn = 0; jn < 4; jn++) {
                    mma_bf16(acc[im][jn], (const uint32_t*)&ah, (const uint32_t*)&bl[jn]);
                    mma_bf16(acc[im][jn], (const uint32_t*)&al, (const uint32_t*)&bh[jn]);
                    mma_bf16(acc[im][jn], (const uint32_t*)&ah, (const uint32_t*)&bh[jn]);
                }
                if (im < 3) { ah = ahn; al = aln; }
            }
        }
    }

    // epilogue
    #pragma unroll
    for (int im = 0; im < 4; im++) {
        const int row0 = by * 128 + wrow * 64 + im * 16 + gid;
        #pragma unroll
        for (int jn = 0; jn < 4; jn++) {
            const int col = bx * 128 + (wcol * 4 + jn) * 8 + tig * 2;
            float2 v0 = make_float2(acc[im][jn][0], acc[im][jn][1]);
            float2 v1 = make_float2(acc[im][jn][2], acc[im][jn][3]);
            if (Cin) {
                float2 r0 = *(const float2*)(Cin + (size_t)row0 * N + col);
                float2 r1 = *(const float2*)(Cin + (size_t)(row0 + 8) * N + col);
                v0.x += r0.x; v0.y += r0.y;
                v1.x += r1.x; v1.y += r1.y;
            }
            if (bias) {
                float b0 = bias[col], b1 = bias[col + 1];
                v0.x += b0; v0.y += b1;
                v1.x += b0; v1.y += b1;
            }
            *(float2*)(C + (size_t)row0 * N + col) = v0;
            *(float2*)(C + (size_t)(row0 + 8) * N + col) = v1;
        }
    }
}

// ---------------- split-K reduce: out = sum_z part[z] + bias -----------------
__global__ void __launch_bounds__(256)
reduceK_kernel(const float* __restrict__ part, const float* __restrict__ bias,
               float* __restrict__ out)
{
    int i4 = (blockIdx.x * 256 + threadIdx.x) * 4;   // over SEQ*OUT
    float4 s = *(const float4*)(part + i4);
    #pragma unroll
    for (int z = 1; z < SPLITK; z++) {
        float4 p = *(const float4*)(part + (size_t)z * SEQ * OUT + i4);
        s.x += p.x; s.y += p.y; s.z += p.z; s.w += p.w;
    }
    int col = i4 % OUT;
    s.x += bias[col]; s.y += bias[col + 1];
    s.z += bias[col + 2]; s.w += bias[col + 3];
    *(float4*)(out + i4) = s;
}

// ---------------- embedding lookup ------------------------------------------
__global__ void embed_kernel(const int* __restrict__ x,
                             const float* __restrict__ embed,
                             float* __restrict__ h)
{
    int s   = blockIdx.x;
    int row = x[s];
    const float4* src = (const float4*)(embed + (size_t)row * H);
    float4*       dst = (float4*)(h + (size_t)s * H);
    for (int i = threadIdx.x; i < H / 4; i += blockDim.x) dst[i] = src[i];
}

// ---------------- RoPE (NeoX split-half), in place; row stride ld ------------
__global__ void rope_kernel(float* __restrict__ q, float* __restrict__ k, int ld)
{
    int s = blockIdx.x;
    for (int idx = threadIdx.x; idx < NH * (HD / 2); idx += blockDim.x) {
        int hh = idx >> 6;
        int i  = idx & 63;
        float inv = (float)exp(-((double)(2 * i) / (double)HD) * log(10000.0));
        float fr  = (float)s * inv;
        float c = cosf(fr), sn = sinf(fr);
        size_t base = (size_t)s * ld + hh * HD;
        float q1 = q[base + i], q2 = q[base + 64 + i];
        q[base + i]      = q1 * c - q2 * sn;
        q[base + 64 + i] = q2 * c + q1 * sn;
        float k1 = k[base + i], k2 = k[base + 64 + i];
        k[base + i]      = k1 * c - k2 * sn;
        k[base + 64 + i] = k2 * c + k1 * sn;
    }
}

// ---------------- causal attention, 8 q-rows per block, online softmax -------
__global__ void __launch_bounds__(128)
attn8_kernel(const float* __restrict__ Q, const float* __restrict__ K,
             const float* __restrict__ V, float* __restrict__ Ot, int ld)
{
    const int qi0 = blockIdx.x * 8, hh = blockIdx.y;
    const int t = threadIdx.x, wq = t >> 5, lid = t & 31;
    __shared__ float q_sh[8][HD];
    __shared__ float p_sh[8][128];
    __shared__ float redm[8][4], reds[8][4];

    #pragma unroll
    for (int r = 0; r < 8; r++)
        q_sh[r][t] = Q[(size_t)(qi0 + r) * ld + hh * HD + t];
    __syncthreads();

    const float scale = 0.08838834764831845f;
    float m_run[8], l_run[8], o_acc[8];
    #pragma unroll
    for (int r = 0; r < 8; r++) { m_run[r] = -1e30f; l_run[r] = 0.f; o_acc[r] = 0.f; }

    const int nkmax = qi0 + 8;
    for (int kb = 0; kb < nkmax; kb += 128) {
        const int k = kb + t;
        float s[8];
        const bool kin = (k < nkmax);
        #pragma unroll
        for (int r = 0; r < 8; r++) s[r] = 0.f;
        if (kin) {
            const float* kr = K + (size_t)k * ld + hh * HD;
            #pragma unroll 8
            for (int d = 0; d < HD; d += 4) {
                float4 kv = *(const float4*)(kr + d);
                #pragma unroll
                for (int r = 0; r < 8; r++) {
                    s[r] = fmaf(kv.x, q_sh[r][d],     s[r]);
                    s[r] = fmaf(kv.y, q_sh[r][d + 1], s[r]);
                    s[r] = fmaf(kv.z, q_sh[r][d + 2], s[r]);
                    s[r] = fmaf(kv.w, q_sh[r][d + 3], s[r]);
                }
            }
        }
        #pragma unroll
        for (int r = 0; r < 8; r++)
            s[r] = (kin && k <= qi0 + r) ? s[r] * scale : -1e30f;

        float mx[8];
        #pragma unroll
        for (int r = 0; r < 8; r++) mx[r] = s[r];
        #pragma unroll
        for (int o = 16; o > 0; o >>= 1)
            #pragma unroll
            for (int r = 0; r < 8; r++)
                mx[r] = fmaxf(mx[r], __shfl_xor_sync(0xffffffffu, mx[r], o));
        if (lid == 0)
            #pragma unroll
            for (int r = 0; r < 8; r++) redm[r][wq] = mx[r];
        __syncthreads();

        float m_new[8], p[8];
        #pragma unroll
        for (int r = 0; r < 8; r++) {
            float bm = fmaxf(fmaxf(redm[r][0], redm[r][1]),
                             fmaxf(redm[r][2], redm[r][3]));
            m_new[r] = fmaxf(m_run[r], bm);
            p[r] = __expf(s[r] - m_new[r]);
            p_sh[r][t] = p[r];
        }
        #pragma unroll
        for (int o = 16; o > 0; o >>= 1)
            #pragma unroll
            for (int r = 0; r < 8; r++)
                p[r] += __shfl_xor_sync(0xffffffffu, p[r], o);
        if (lid == 0)
            #pragma unroll
            for (int r = 0; r < 8; r++) reds[r][wq] = p[r];
        __syncthreads();

        #pragma unroll
        for (int r = 0; r < 8; r++) {
            float ps = reds[r][0] + reds[r][1] + reds[r][2] + reds[r][3];
            float corr = __expf(m_run[r] - m_new[r]);
            l_run[r] = l_run[r] * corr + ps;
            o_acc[r] *= corr;
            m_run[r] = m_new[r];
        }

        const int kmax = min(128, nkmax - kb);
        const float* vb = V + (size_t)kb * ld + hh * HD + t;
        for (int c4 = 0; c4 * 4 < kmax; c4++) {
            float pv[8][4];
            #pragma unroll
            for (int r = 0; r < 8; r++) {
                float4 p4 = *(const float4*)&p_sh[r][c4 * 4];
                pv[r][0] = p4.x; pv[r][1] = p4.y; pv[r][2] = p4.z; pv[r][3] = p4.w;
            }
            #pragma unroll
            for (int j = 0; j < 4; j++) {
                float v = vb[(size_t)(c4 * 4 + j) * ld];
                #pragma unroll
                for (int r = 0; r < 8; r++)
                    o_acc[r] = fmaf(pv[r][j], v, o_acc[r]);
            }
        }
        __syncthreads();
    }
    #pragma unroll
    for (int r = 0; r < 8; r++)
        Ot[(size_t)(qi0 + r) * H + hh * HD + t] = o_acc[r] / l_run[r];
}

// ---------------- launcher ---------------------------------------------------
extern "C" void kernel_launch(void* const* d_in, const int* in_sizes, int n_in,
                              void* d_out, int out_size)
{
    const int*   x     = (const int*)  d_in[0];
    const float* embed = (const float*)d_in[1];
    const float* Wq    = (const float*)d_in[2];
    const float* Wk    = (const float*)d_in[3];
    const float* Wv    = (const float*)d_in[4];
    const float* Wo    = (const float*)d_in[5];
    const float* Wg    = (const float*)d_in[6];
    const float* Wu    = (const float*)d_in[7];
    const float* Wd    = (const float*)d_in[8];
    const float* ln1   = (const float*)d_in[9];
    const float* ln2   = (const float*)d_in[10];
    const float* lnf   = (const float*)d_in[11];
    const float* Wout  = (const float*)d_in[12];
    const float* bout  = (const float*)d_in[13];
    float* out = (float*)d_out;

    float *h, *qkv, *ao, *gu, *rs, *part;
    uint4* a4;
    uint2 *wqkv, *wo, *wgu, *wd, *wout;
    cudaGetSymbolAddress((void**)&h,    g_h);
    cudaGetSymbolAddress((void**)&qkv,  g_qkv);
    cudaGetSymbolAddress((void**)&ao,   g_ao);
    cudaGetSymbolAddress((void**)&gu,   g_gu);
    cudaGetSymbolAddress((void**)&rs,   g_rs);
    cudaGetSymbolAddress((void**)&part, g_part);
    cudaGetSymbolAddress((void**)&a4,   g_a4);
    cudaGetSymbolAddress((void**)&wqkv, g_wqkv);
    cudaGetSymbolAddress((void**)&wo,   g_wo);
    cudaGetSymbolAddress((void**)&wgu,  g_wgu);
    cudaGetSymbolAddress((void**)&wd,   g_wd);
    cudaGetSymbolAddress((void**)&wout, g_wout);

    cudaFuncSetAttribute(tgemm2_kernel,
                         cudaFuncAttributeMaxDynamicSharedMemorySize, GSM3);

    // ---- single side stream for weight conversion ----
    cudaStream_t s2;
    cudaStreamCreateWithFlags(&s2, cudaStreamNonBlocking);
    cudaEvent_t eFork;
    cudaEventCreateWithFlags(&eFork, cudaEventDisableTiming);
    cudaEvent_t eW[NL * 4 + 1];
    for (int i = 0; i < NL * 4 + 1; i++)
        cudaEventCreateWithFlags(&eW[i], cudaEventDisableTiming);

    dim3 grid_h(H / 128, SEQ / 128);
    dim3 grid_qkv(3 * H / 128, SEQ / 128);
    dim3 grid_gu(2 * FF / 128, SEQ / 128);
    dim3 cv_h(MB_S, H / 128);
    dim3 cv_f(MB_S, FF / 128);

    embed_kernel<<<SEQ, 256>>>(x, embed, h);
    rms_scale_kernel<<<SEQ, 256>>>(h, rs);
    convAS_kernel<<<cv_h, 256>>>(h, rs, ln1, a4, SEQ, H);

    cudaEventRecord(eFork, 0);
    cudaStreamWaitEvent(s2, eFork, 0);

    convB_qkv_kernel<<<dim3(H / 16, H / 128, 3), 256, 0, s2>>>(Wq, Wk, Wv, wqkv);
    cudaEventRecord(eW[0], s2);
    convB_kernel<<<dim3(H / 16, H / 128), 256, 0, s2>>>(Wo, wo, H, H, H / 8, 0);
    cudaEventRecord(eW[1], s2);

    cudaStreamWaitEvent(0, eW[0], 0);
    tgemm2_kernel<<<grid_qkv, 256, GSM3>>>(SEQ, 3 * H, KB_H, KB_H / 2, a4,
                                           wqkv, nullptr, nullptr, qkv);

    // remaining weight conversions on s2
    convB_kernel<<<dim3(H / 16, FF / 128), 256, 0, s2>>>(Wg, wgu, H, FF, 2 * FF / 8, 0);
    convB_kernel<<<dim3(H / 16, FF / 128), 256, 0, s2>>>(Wu, wgu, H, FF, 2 * FF / 8, FF / 128);
    cudaEventRecord(eW[2], s2);
    convB_kernel<<<dim3(FF / 16, H / 128), 256, 0, s2>>>(Wd, wd, FF, H, H / 8, 0);
    cudaEventRecord(eW[3], s2);
    for (int l = 1; l < NL; l++) {
        convB_qkv_kernel<<<dim3(H / 16, H / 128, 3), 256, 0, s2>>>(
            Wq + (size_t)l * H * H, Wk + (size_t)l * H * H, Wv + (size_t)l * H * H,
            wqkv + l * SQKV_L);
        cudaEventRecord(eW[l * 4 + 0], s2);
        convB_kernel<<<dim3(H / 16, H / 128), 256, 0, s2>>>(Wo + (size_t)l * H * H, wo + l * SWQ_L, H, H, H / 8, 0);
        cudaEventRecord(eW[l * 4 + 1], s2);
        uint2* wgu_l = wgu + l * SWGU_L;
        convB_kernel<<<dim3(H / 16, FF / 128), 256, 0, s2>>>(Wg + (size_t)l * H * FF, wgu_l, H, FF, 2 * FF / 8, 0);
        convB_kernel<<<dim3(H / 16, FF / 128), 256, 0, s2>>>(Wu + (size_t)l * H * FF, wgu_l, H, FF, 2 * FF / 8, FF / 128);
        cudaEventRecord(eW[l * 4 + 2], s2);
        convB_kernel<<<dim3(FF / 16, H / 128), 256, 0, s2>>>(Wd + (size_t)l * FF * H, wd + l * SWD_L, FF, H, H / 8, 0);
        cudaEventRecord(eW[l * 4 + 3], s2);
    }
    convB_kernel<<<dim3(H / 16, OUT / 128), 256, 0, s2>>>(Wout, wout, H, OUT, OUT / 8, 0);
    cudaEventRecord(eW[NL * 4], s2);

    // ---- main stream: rest of the forward pass ----
    for (int l = 0; l < NL; l++) {
        if (l > 0) {
            rms_scale_kernel<<<SEQ, 256>>>(h, rs);
            convAS_kernel<<<cv_h, 256>>>(h, rs, ln1 + (size_t)l * H, a4, SEQ, H);
            cudaStreamWaitEvent(0, eW[l * 4 + 0], 0);
            tgemm2_kernel<<<grid_qkv, 256, GSM3>>>(SEQ, 3 * H, KB_H, KB_H / 2, a4,
                                                   wqkv + l * SQKV_L, nullptr, nullptr, qkv);
        }
        rope_kernel<<<SEQ, 256>>>(qkv, qkv + H, 3 * H);
        attn8_kernel<<<dim3(SEQ / 8, NH), 128>>>(qkv, qkv + H, qkv + 2 * H, ao, 3 * H);
        convA_kernel<<<cv_h, 256>>>(ao, a4, SEQ, H);
        cudaStreamWaitEvent(0, eW[l * 4 + 1], 0);
        tgemm2_kernel<<<grid_h, 256, GSM3>>>(SEQ, H, KB_H, KB_H / 2, a4,
                                             wo + l * SWQ_L, h, nullptr, h);

        rms_scale_kernel<<<SEQ, 256>>>(h, rs);
        convAS_kernel<<<cv_h, 256>>>(h, rs, ln2 + (size_t)l * H, a4, SEQ, H);
        cudaStreamWaitEvent(0, eW[l * 4 + 2], 0);
        tgemm2_kernel<<<grid_gu, 256, GSM3>>>(SEQ, 2 * FF, KB_H, KB_H / 2, a4,
                                              wgu + l * SWGU_L, nullptr, nullptr, gu);
        siluconv_kernel<<<cv_f, 256>>>(gu, a4, SEQ, FF);
        cudaStreamWaitEvent(0, eW[l * 4 + 3], 0);
        tgemm2_kernel<<<grid_h, 256, GSM3>>>(SEQ, H, KB_F, KB_F / 2, a4,
                                             wd + l * SWD_L, h, nullptr, h);
    }

    rms_scale_kernel<<<SEQ, 256>>>(h, rs);
    convAS_kernel<<<cv_h, 256>>>(h, rs, lnf, a4, SEQ, H);
    cudaStreamWaitEvent(0, eW[NL * 4], 0);
    tgemm2_kernel<<<dim3(OUT / 128, SEQ / 128, SPLITK), 256, GSM3>>>(
        SEQ, OUT, KB_H, KB_H / (2 * SPLITK), a4, wout, nullptr, nullptr, part);
    reduceK_kernel<<<SEQ * OUT / 4 / 256, 256>>>(part, bout, out);
}

// round 17
// speedup vs baseline: 1.7788x; 1.7788x over previous
#include <cuda_runtime.h>
#include <cstdint>
#include <math.h>

#define H    4096
#define NH   32
#define HD   128
#define FF   11008
#define SEQ  1024
#define NL   2
#define OUT  512

#define KB_H (H / 16)     // 256
#define KB_F (FF / 16)    // 688
#define MB_S (SEQ / 16)   // 64
#define SPLITK 4

// ---------------- scratch (static device globals; no runtime alloc) ----------
__device__ float g_h  [SEQ * H];
__device__ float g_qkv[SEQ * 3 * H];
__device__ float g_ao [SEQ * H];
__device__ float g_gu [SEQ * 2 * FF];
__device__ float g_rs [SEQ];
__device__ float g_part[SPLITK * SEQ * OUT];

// split activations (A-side), sized for the largest (K=FF)
__device__ uint4 g_a4[(size_t)2 * MB_S * KB_F * 32];

// split weights (B-side): ONE uint4 per (n8-block, k16-block, lane):
// {hi.r0, hi.r1, lo.r0, lo.r1}
#define SWQ4  ((size_t)(H  / 8) * KB_H * 32)
#define SWGU4 ((size_t)(2 * FF / 8) * KB_H * 32)
#define SWD4  ((size_t)(H  / 8) * KB_F * 32)
#define SWOUT4 ((size_t)(OUT/ 8) * KB_H * 32)
#define SQKV4 ((size_t)(3 * H / 8) * KB_H * 32)
__device__ uint4 g_wqkv[NL * SQKV4];
__device__ uint4 g_wo [NL * SWQ4];
__device__ uint4 g_wgu[NL * SWGU4];
__device__ uint4 g_wd [NL * SWD4];
__device__ uint4 g_wout[SWOUT4];

// ---------------- helpers ----------------------------------------------------
__device__ __forceinline__ uint32_t smem_u32(const void* p) {
    uint32_t a;
    asm("{ .reg .u64 t; cvta.to.shared.u64 t, %1; cvt.u32.u64 %0, t; }"
        : "=r"(a) : "l"(p));
    return a;
}
__device__ __forceinline__ void cp16(uint32_t dst, const void* src) {
    asm volatile("cp.async.cg.shared.global [%0], [%1], 16;"
                 :: "r"(dst), "l"(src));
}
// split (f0,f1) -> packed bf16x2 hi (low16 = f0) and lo (residuals)
__device__ __forceinline__ void split2(float2 f, uint32_t& hi, uint32_t& lo) {
    asm("cvt.rn.bf16x2.f32 %0, %1, %2;" : "=r"(hi) : "f"(f.y), "f"(f.x));
    float h0 = __uint_as_float(hi << 16);
    float h1 = __uint_as_float(hi & 0xffff0000u);
    float r0 = f.x - h0;
    float r1 = f.y - h1;
    asm("cvt.rn.bf16x2.f32 %0, %1, %2;" : "=r"(lo) : "f"(r1), "f"(r0));
}
__device__ __forceinline__ void mma_bf16(float* d, const uint32_t* a,
                                         const uint32_t* b) {
    asm volatile(
        "mma.sync.aligned.m16n8k16.row.col.f32.bf16.bf16.f32 "
        "{%0,%1,%2,%3}, {%4,%5,%6,%7}, {%8,%9}, {%0,%1,%2,%3};"
        : "+f"(d[0]), "+f"(d[1]), "+f"(d[2]), "+f"(d[3])
        : "r"(a[0]), "r"(a[1]), "r"(a[2]), "r"(a[3]),
          "r"(b[0]), "r"(b[1]));
}

// ---------------- shared fragment-writer (16x128 smem tile -> a4) ------------
__device__ __forceinline__ void write_frags(const float (*Xs)[132],
                                            uint4* __restrict__ dst,
                                            int mb, int kb0, int MB, int KB,
                                            int tid, int nthreads)
{
    for (int idx = tid; idx < 512; idx += nthreads) {
        int l = idx & 31, kbl = (idx >> 5) & 7, h = idx >> 8;
        int gid = l >> 2, tig = l & 3;
        int c0 = kbl * 16 + tig * 2;
        float2 p00 = make_float2(Xs[gid][c0],         Xs[gid][c0 + 1]);
        float2 p10 = make_float2(Xs[gid + 8][c0],     Xs[gid + 8][c0 + 1]);
        float2 p01 = make_float2(Xs[gid][c0 + 8],     Xs[gid][c0 + 9]);
        float2 p11 = make_float2(Xs[gid + 8][c0 + 8], Xs[gid + 8][c0 + 9]);
        uint32_t h00, l00, h10, l10, h01, l01, h11, l11;
        split2(p00, h00, l00); split2(p10, h10, l10);
        split2(p01, h01, l01); split2(p11, h11, l11);
        uint4 o = h ? make_uint4(l00, l10, l01, l11)
                    : make_uint4(h00, h10, h01, h11);
        dst[(((size_t)h * MB + mb) * KB + kb0 + kbl) * 32 + l] = o;
    }
}

// ---------------- rms scale: rs[row] = rsqrt(mean(x^2)+eps) ------------------
__global__ void __launch_bounds__(256)
rms_scale_kernel(const float* __restrict__ x, float* __restrict__ rs)
{
    int row = blockIdx.x;
    const float* xr = x + (size_t)row * H;
    float ss = 0.f;
    for (int i = threadIdx.x * 4; i < H; i += 1024) {
        float4 v = *(const float4*)(xr + i);
        ss += v.x * v.x + v.y * v.y + v.z * v.z + v.w * v.w;
    }
    __shared__ float red[8];
    #pragma unroll
    for (int o = 16; o > 0; o >>= 1) ss += __shfl_xor_sync(0xffffffffu, ss, o);
    if ((threadIdx.x & 31) == 0) red[threadIdx.x >> 5] = ss;
    __syncthreads();
    if (threadIdx.x == 0) {
        float tot = 0.f;
        #pragma unroll
        for (int i = 0; i < 8; i++) tot += red[i];
        rs[row] = rsqrtf(tot / (float)H + 1e-6f);
    }
}

// ---------------- convAS: split X[M][K] * rs[row] * w[col] -> a4 -------------
__global__ void __launch_bounds__(256)
convAS_kernel(const float* __restrict__ X, const float* __restrict__ rs,
              const float* __restrict__ w, uint4* __restrict__ dst,
              int M, int K)
{
    __shared__ float Xs[16][132];
    const int mb = blockIdx.x, kc = blockIdx.y;
    const int tid = threadIdx.x;
    #pragma unroll
    for (int it = 0; it < 2; it++) {
        int f4 = it * 256 + tid;
        int r = f4 >> 5, c4 = f4 & 31;
        float4 v = *(const float4*)(X + (size_t)(mb * 16 + r) * K + kc * 128 + c4 * 4);
        float sc = rs[mb * 16 + r];
        float4 wv = *(const float4*)(w + kc * 128 + c4 * 4);
        Xs[r][c4 * 4 + 0] = v.x * sc * wv.x;
        Xs[r][c4 * 4 + 1] = v.y * sc * wv.y;
        Xs[r][c4 * 4 + 2] = v.z * sc * wv.z;
        Xs[r][c4 * 4 + 3] = v.w * sc * wv.w;
    }
    __syncthreads();
    write_frags(Xs, dst, mb, kc * 8, M >> 4, K >> 4, tid, 256);
}

// ---------------- convA (plain): split X[M][K] -> a4 -------------------------
__global__ void __launch_bounds__(256)
convA_kernel(const float* __restrict__ X, uint4* __restrict__ dst, int M, int K)
{
    __shared__ float Xs[16][132];
    const int mb = blockIdx.x, kc = blockIdx.y;
    const int tid = threadIdx.x;
    #pragma unroll
    for (int it = 0; it < 2; it++) {
        int f4 = it * 256 + tid;
        int r = f4 >> 5, c4 = f4 & 31;
        float4 v = *(const float4*)(X + (size_t)(mb * 16 + r) * K + kc * 128 + c4 * 4);
        Xs[r][c4 * 4 + 0] = v.x; Xs[r][c4 * 4 + 1] = v.y;
        Xs[r][c4 * 4 + 2] = v.z; Xs[r][c4 * 4 + 3] = v.w;
    }
    __syncthreads();
    write_frags(Xs, dst, mb, kc * 8, M >> 4, K >> 4, tid, 256);
}

// ---------------- siluconv: a4 = split(silu(gu[:,k]) * gu[:,K+k]) ------------
__global__ void __launch_bounds__(256)
siluconv_kernel(const float* __restrict__ gu, uint4* __restrict__ dst,
                int M, int K)
{
    __shared__ float Xs[16][132];
    const int mb = blockIdx.x, kc = blockIdx.y;
    const int tid = threadIdx.x;
    #pragma unroll
    for (int it = 0; it < 2; it++) {
        int f4 = it * 256 + tid;
        int r = f4 >> 5, c4 = f4 & 31;
        const float* rowp = gu + (size_t)(mb * 16 + r) * 2 * K + kc * 128 + c4 * 4;
        float4 g = *(const float4*)(rowp);
        float4 u = *(const float4*)(rowp + K);
        Xs[r][c4 * 4 + 0] = g.x / (1.f + __expf(-g.x)) * u.x;
        Xs[r][c4 * 4 + 1] = g.y / (1.f + __expf(-g.y)) * u.y;
        Xs[r][c4 * 4 + 2] = g.z / (1.f + __expf(-g.z)) * u.z;
        Xs[r][c4 * 4 + 3] = g.w / (1.f + __expf(-g.w)) * u.w;
    }
    __syncthreads();
    write_frags(Xs, dst, mb, kc * 8, M >> 4, K >> 4, tid, 256);
}

// ---------------- convert B-side W[K][N] -> interleaved uint4 fragments ------
// dst[(n8)*KB + kb][lane] = {hi.r0, hi.r1, lo.r0, lo.r1}
__global__ void __launch_bounds__(256)
convB_kernel(const float* __restrict__ W, uint4* __restrict__ dst, int K, int N,
             int n8_off)
{
    __shared__ float Ws[16][132];
    const int kb = blockIdx.x, nc = blockIdx.y;
    const int tid = threadIdx.x;
    const int KB = K >> 4;
    #pragma unroll
    for (int it = 0; it < 2; it++) {
        int f4 = it * 256 + tid;
        int r = f4 >> 5, c4 = f4 & 31;
        float4 v = *(const float4*)(W + (size_t)(kb * 16 + r) * N + nc * 128 + c4 * 4);
        Ws[r][c4 * 4 + 0] = v.x; Ws[r][c4 * 4 + 1] = v.y;
        Ws[r][c4 * 4 + 2] = v.z; Ws[r][c4 * 4 + 3] = v.w;
    }
    __syncthreads();
    #pragma unroll
    for (int it = 0; it < 2; it++) {
        int idx = it * 256 + tid;
        int l = idx & 31, nbl = idx >> 5;   // 0..15
        int gid = l >> 2, tig = l & 3;
        int n = nbl * 8 + gid;
        float2 q0 = make_float2(Ws[2 * tig][n],     Ws[2 * tig + 1][n]);
        float2 q1 = make_float2(Ws[2 * tig + 8][n], Ws[2 * tig + 9][n]);
        uint32_t qh0, ql0, qh1, ql1;
        split2(q0, qh0, ql0); split2(q1, qh1, ql1);
        dst[((size_t)(n8_off + nc * 16 + nbl) * KB + kb) * 32 + l] =
            make_uint4(qh0, qh1, ql0, ql1);
    }
}

// ---------------- convB_qkv: 3-in-1 (blockIdx.z selects Wq/Wk/Wv) ------------
__global__ void __launch_bounds__(256)
convB_qkv_kernel(const float* __restrict__ Wq, const float* __restrict__ Wk,
                 const float* __restrict__ Wv, uint4* __restrict__ dst)
{
    __shared__ float Ws[16][132];
    const int kb = blockIdx.x, nc = blockIdx.y, z = blockIdx.z;
    const int tid = threadIdx.x;
    const int KB = KB_H;
    const int n8_off = z * (H / 8);
    const float* W = (z == 0) ? Wq : (z == 1) ? Wk : Wv;
    #pragma unroll
    for (int it = 0; it < 2; it++) {
        int f4 = it * 256 + tid;
        int r = f4 >> 5, c4 = f4 & 31;
        float4 v = *(const float4*)(W + (size_t)(kb * 16 + r) * H + nc * 128 + c4 * 4);
        Ws[r][c4 * 4 + 0] = v.x; Ws[r][c4 * 4 + 1] = v.y;
        Ws[r][c4 * 4 + 2] = v.z; Ws[r][c4 * 4 + 3] = v.w;
    }
    __syncthreads();
    #pragma unroll
    for (int it = 0; it < 2; it++) {
        int idx = it * 256 + tid;
        int l = idx & 31, nbl = idx >> 5;
        int gid = l >> 2, tig = l & 3;
        int n = nbl * 8 + gid;
        float2 q0 = make_float2(Ws[2 * tig][n],     Ws[2 * tig + 1][n]);
        float2 q1 = make_float2(Ws[2 * tig + 8][n], Ws[2 * tig + 9][n]);
        uint32_t qh0, ql0, qh1, ql1;
        split2(q0, qh0, ql0); split2(q1, qh1, ql1);
        dst[((size_t)(n8_off + nc * 16 + nbl) * KB + kb) * 32 + l] =
            make_uint4(qh0, qh1, ql0, ql1);
    }
}

// ---------------- split-bf16 tensor-core GEMM, 3-stage pipeline --------------
// A staged in SMEM (16KB/stage) + B staged interleaved uint4 (16KB/stage).
// KBs: KB stride; NCr: chunks per CTA; blockIdx.z = split-K partition.
#define BUF 32768
#define NST 3
#define GSM3 (NST * BUF)
__global__ void __launch_bounds__(256, 2)
tgemm2_kernel(int M, int N, int KBs, int NCr,
              const uint4* __restrict__ A4, const uint4* __restrict__ B4,
              const float* __restrict__ Cin, const float* __restrict__ bias,
              float* __restrict__ C)
{
    extern __shared__ char smem[];
    const uint32_t sb = smem_u32(smem);
    const int tid = threadIdx.x;
    const int wid = tid >> 5, lane = tid & 31;
    const int wrow = wid >> 2, wcol = wid & 3;
    const int gid = lane >> 2, tig = lane & 3;
    const int bx = blockIdx.x, by = blockIdx.y;
    const int kz = blockIdx.z;

    const int KB = KBs;
    const size_t hA = (size_t)(M >> 4) * KB * 32;   // uint4 units (hi/lo halves)
    const int NC = NCr;
    const int kbz = kz * NCr * 2;
    C += (size_t)kz * M * N;

    auto issue = [&](int c) {
        if (c < NC) {
            const int kb0 = kbz + c * 2;
            uint32_t dstA = sb + (uint32_t)(c % NST) * BUF;
            uint32_t dstB = dstA + 16384;
            #pragma unroll
            for (int it = 0; it < 4; it++) {
                int idx = it * 256 + tid;
                int l = idx & 31, kb = (idx >> 5) & 1, mb = (idx >> 6) & 7, h = idx >> 9;
                const uint4* src = A4 + (size_t)h * hA
                                 + ((size_t)(by * 8 + mb) * KB + kb0 + kb) * 32 + l;
                cp16(dstA + idx * 16, src);
            }
            #pragma unroll
            for (int it = 0; it < 4; it++) {
                int idx = it * 256 + tid;
                int l = idx & 31, kb = (idx >> 5) & 1, nb = idx >> 6;  // nb 0..15
                const uint4* src = B4
                                 + ((size_t)(bx * 16 + nb) * KB + kb0 + kb) * 32 + l;
                cp16(dstB + idx * 16, src);
            }
        }
        asm volatile("cp.async.commit_group;" ::: "memory");
    };

    float acc[4][4][4];
    #pragma unroll
    for (int i = 0; i < 4; i++)
        #pragma unroll
        for (int j = 0; j < 4; j++)
            #pragma unroll
            for (int r = 0; r < 4; r++) acc[i][j][r] = 0.f;

    issue(0);
    issue(1);

    for (int c = 0; c < NC; c++) {
        asm volatile("cp.async.wait_group 1;" ::: "memory");
        __syncthreads();
        issue(c + 2);

        const uint4* As4 = (const uint4*)(smem + (c % NST) * BUF);          // [2][8][2][32]
        const uint4* Bs4 = (const uint4*)(smem + (c % NST) * BUF + 16384);  // [16][2][32]

        #pragma unroll
        for (int ks = 0; ks < 2; ks++) {
            uint4 bq[4];
            #pragma unroll
            for (int jn = 0; jn < 4; jn++) {
                int nb = wcol * 4 + jn;
                bq[jn] = Bs4[(nb * 2 + ks) * 32 + lane];
            }
            #pragma unroll
            for (int im = 0; im < 4; im++) {
                int mb = wrow * 4 + im;
                uint4 ah = As4[((0 * 8 + mb) * 2 + ks) * 32 + lane];
                uint4 al = As4[((1 * 8 + mb) * 2 + ks) * 32 + lane];
                #pragma unroll
                for (int jn = 0; jn < 4; jn++) {
                    const uint32_t bh[2] = { bq[jn].x, bq[jn].y };
                    const uint32_t bl[2] = { bq[jn].z, bq[jn].w };
                    mma_bf16(acc[im][jn], (const uint32_t*)&ah, bl);
                    mma_bf16(acc[im][jn], (const uint32_t*)&al, bh);
                    mma_bf16(acc[im][jn], (const uint32_t*)&ah, bh);
                }
            }
        }
    }

    // epilogue
    #pragma unroll
    for (int im = 0; im < 4; im++) {
        const int row0 = by * 128 + wrow * 64 + im * 16 + gid;
        #pragma unroll
        for (int jn = 0; jn < 4; jn++) {
            const int col = bx * 128 + (wcol * 4 + jn) * 8 + tig * 2;
            float2 v0 = make_float2(acc[im][jn][0], acc[im][jn][1]);
            float2 v1 = make_float2(acc[im][jn][2], acc[im][jn][3]);
            if (Cin) {
                float2 r0 = *(const float2*)(Cin + (size_t)row0 * N + col);
                float2 r1 = *(const float2*)(Cin + (size_t)(row0 + 8) * N + col);
                v0.x += r0.x; v0.y += r0.y;
                v1.x += r1.x; v1.y += r1.y;
            }
            if (bias) {
                float b0 = bias[col], b1 = bias[col + 1];
                v0.x += b0; v0.y += b1;
                v1.x += b0; v1.y += b1;
            }
            *(float2*)(C + (size_t)row0 * N + col) = v0;
            *(float2*)(C + (size_t)(row0 + 8) * N + col) = v1;
        }
    }
}

// ---------------- split-K reduce: out = sum_z part[z] + bias -----------------
__global__ void __launch_bounds__(256)
reduceK_kernel(const float* __restrict__ part, const float* __restrict__ bias,
               float* __restrict__ out)
{
    int i4 = (blockIdx.x * 256 + threadIdx.x) * 4;   // over SEQ*OUT
    float4 s = *(const float4*)(part + i4);
    #pragma unroll
    for (int z = 1; z < SPLITK; z++) {
        float4 p = *(const float4*)(part + (size_t)z * SEQ * OUT + i4);
        s.x += p.x; s.y += p.y; s.z += p.z; s.w += p.w;
    }
    int col = i4 % OUT;
    s.x += bias[col]; s.y += bias[col + 1];
    s.z += bias[col + 2]; s.w += bias[col + 3];
    *(float4*)(out + i4) = s;
}

// ---------------- embedding lookup ------------------------------------------
__global__ void embed_kernel(const int* __restrict__ x,
                             const float* __restrict__ embed,
                             float* __restrict__ h)
{
    int s   = blockIdx.x;
    int row = x[s];
    const float4* src = (const float4*)(embed + (size_t)row * H);
    float4*       dst = (float4*)(h + (size_t)s * H);
    for (int i = threadIdx.x; i < H / 4; i += blockDim.x) dst[i] = src[i];
}

// ---------------- RoPE (NeoX split-half), in place; row stride ld ------------
__global__ void rope_kernel(float* __restrict__ q, float* __restrict__ k, int ld)
{
    int s = blockIdx.x;
    for (int idx = threadIdx.x; idx < NH * (HD / 2); idx += blockDim.x) {
        int hh = idx >> 6;
        int i  = idx & 63;
        float inv = (float)exp(-((double)(2 * i) / (double)HD) * log(10000.0));
        float fr  = (float)s * inv;
        float c = cosf(fr), sn = sinf(fr);
        size_t base = (size_t)s * ld + hh * HD;
        float q1 = q[base + i], q2 = q[base + 64 + i];
        q[base + i]      = q1 * c - q2 * sn;
        q[base + 64 + i] = q2 * c + q1 * sn;
        float k1 = k[base + i], k2 = k[base + 64 + i];
        k[base + i]      = k1 * c - k2 * sn;
        k[base + 64 + i] = k2 * c + k1 * sn;
    }
}

// ---------------- causal attention, 8 q-rows per block, online softmax -------
__global__ void __launch_bounds__(128)
attn8_kernel(const float* __restrict__ Q, const float* __restrict__ K,
             const float* __restrict__ V, float* __restrict__ Ot, int ld)
{
    const int qi0 = blockIdx.x * 8, hh = blockIdx.y;
    const int t = threadIdx.x, wq = t >> 5, lid = t & 31;
    __shared__ float q_sh[8][HD];
    __shared__ float p_sh[8][128];
    __shared__ float redm[8][4], reds[8][4];

    #pragma unroll
    for (int r = 0; r < 8; r++)
        q_sh[r][t] = Q[(size_t)(qi0 + r) * ld + hh * HD + t];
    __syncthreads();

    const float scale = 0.08838834764831845f;
    float m_run[8], l_run[8], o_acc[8];
    #pragma unroll
    for (int r = 0; r < 8; r++) { m_run[r] = -1e30f; l_run[r] = 0.f; o_acc[r] = 0.f; }

    const int nkmax = qi0 + 8;
    for (int kb = 0; kb < nkmax; kb += 128) {
        const int k = kb + t;
        float s[8];
        const bool kin = (k < nkmax);
        #pragma unroll
        for (int r = 0; r < 8; r++) s[r] = 0.f;
        if (kin) {
            const float* kr = K + (size_t)k * ld + hh * HD;
            #pragma unroll 8
            for (int d = 0; d < HD; d += 4) {
                float4 kv = *(const float4*)(kr + d);
                #pragma unroll
                for (int r = 0; r < 8; r++) {
                    s[r] = fmaf(kv.x, q_sh[r][d],     s[r]);
                    s[r] = fmaf(kv.y, q_sh[r][d + 1], s[r]);
                    s[r] = fmaf(kv.z, q_sh[r][d + 2], s[r]);
                    s[r] = fmaf(kv.w, q_sh[r][d + 3], s[r]);
                }
            }
        }
        #pragma unroll
        for (int r = 0; r < 8; r++)
            s[r] = (kin && k <= qi0 + r) ? s[r] * scale : -1e30f;

        float mx[8];
        #pragma unroll
        for (int r = 0; r < 8; r++) mx[r] = s[r];
        #pragma unroll
        for (int o = 16; o > 0; o >>= 1)
            #pragma unroll
            for (int r = 0; r < 8; r++)
                mx[r] = fmaxf(mx[r], __shfl_xor_sync(0xffffffffu, mx[r], o));
        if (lid == 0)
            #pragma unroll
            for (int r = 0; r < 8; r++) redm[r][wq] = mx[r];
        __syncthreads();

        float m_new[8], p[8];
        #pragma unroll
        for (int r = 0; r < 8; r++) {
            float bm = fmaxf(fmaxf(redm[r][0], redm[r][1]),
                             fmaxf(redm[r][2], redm[r][3]));
            m_new[r] = fmaxf(m_run[r], bm);
            p[r] = __expf(s[r] - m_new[r]);
            p_sh[r][t] = p[r];
        }
        #pragma unroll
        for (int o = 16; o > 0; o >>= 1)
            #pragma unroll
            for (int r = 0; r < 8; r++)
                p[r] += __shfl_xor_sync(0xffffffffu, p[r], o);
        if (lid == 0)
            #pragma unroll
            for (int r = 0; r < 8; r++) reds[r][wq] = p[r];
        __syncthreads();

        #pragma unroll
        for (int r = 0; r < 8; r++) {
            float ps = reds[r][0] + reds[r][1] + reds[r][2] + reds[r][3];
            float corr = __expf(m_run[r] - m_new[r]);
            l_run[r] = l_run[r] * corr + ps;
            o_acc[r] *= corr;
            m_run[r] = m_new[r];
        }

        const int kmax = min(128, nkmax - kb);
        const float* vb = V + (size_t)kb * ld + hh * HD + t;
        for (int c4 = 0; c4 * 4 < kmax; c4++) {
            float pv[8][4];
            #pragma unroll
            for (int r = 0; r < 8; r++) {
                float4 p4 = *(const float4*)&p_sh[r][c4 * 4];
                pv[r][0] = p4.x; pv[r][1] = p4.y; pv[r][2] = p4.z; pv[r][3] = p4.w;
            }
            #pragma unroll
            for (int j = 0; j < 4; j++) {
                float v = vb[(size_t)(c4 * 4 + j) * ld];
                #pragma unroll
                for (int r = 0; r < 8; r++)
                    o_acc[r] = fmaf(pv[r][j], v, o_acc[r]);
            }
        }
        __syncthreads();
    }
    #pragma unroll
    for (int r = 0; r < 8; r++)
        Ot[(size_t)(qi0 + r) * H + hh * HD + t] = o_acc[r] / l_run[r];
}

// ---------------- launcher ---------------------------------------------------
extern "C" void kernel_launch(void* const* d_in, const int* in_sizes, int n_in,
                              void* d_out, int out_size)
{
    const int*   x     = (const int*)  d_in[0];
    const float* embed = (const float*)d_in[1];
    const float* Wq    = (const float*)d_in[2];
    const float* Wk    = (const float*)d_in[3];
    const float* Wv    = (const float*)d_in[4];
    const float* Wo    = (const float*)d_in[5];
    const float* Wg    = (const float*)d_in[6];
    const float* Wu    = (const float*)d_in[7];
    const float* Wd    = (const float*)d_in[8];
    const float* ln1   = (const float*)d_in[9];
    const float* ln2   = (const float*)d_in[10];
    const float* lnf   = (const float*)d_in[11];
    const float* Wout  = (const float*)d_in[12];
    const float* bout  = (const float*)d_in[13];
    float* out = (float*)d_out;

    float *h, *qkv, *ao, *gu, *rs, *part;
    uint4* a4;
    uint4 *wqkv, *wo, *wgu, *wd, *wout;
    cudaGetSymbolAddress((void**)&h,    g_h);
    cudaGetSymbolAddress((void**)&qkv,  g_qkv);
    cudaGetSymbolAddress((void**)&ao,   g_ao);
    cudaGetSymbolAddress((void**)&gu,   g_gu);
    cudaGetSymbolAddress((void**)&rs,   g_rs);
    cudaGetSymbolAddress((void**)&part, g_part);
    cudaGetSymbolAddress((void**)&a4,   g_a4);
    cudaGetSymbolAddress((void**)&wqkv, g_wqkv);
    cudaGetSymbolAddress((void**)&wo,   g_wo);
    cudaGetSymbolAddress((void**)&wgu,  g_wgu);
    cudaGetSymbolAddress((void**)&wd,   g_wd);
    cudaGetSymbolAddress((void**)&wout, g_wout);

    cudaFuncSetAttribute(tgemm2_kernel,
                         cudaFuncAttributeMaxDynamicSharedMemorySize, GSM3);

    // ---- single side stream for weight conversion ----
    cudaStream_t s2;
    cudaStreamCreateWithFlags(&s2, cudaStreamNonBlocking);
    cudaEvent_t eFork;
    cudaEventCreateWithFlags(&eFork, cudaEventDisableTiming);
    cudaEvent_t eW[NL * 4 + 1];
    for (int i = 0; i < NL * 4 + 1; i++)
        cudaEventCreateWithFlags(&eW[i], cudaEventDisableTiming);

    dim3 grid_h(H / 128, SEQ / 128);
    dim3 grid_qkv(3 * H / 128, SEQ / 128);
    dim3 grid_gu(2 * FF / 128, SEQ / 128);
    dim3 cv_h(MB_S, H / 128);
    dim3 cv_f(MB_S, FF / 128);

    embed_kernel<<<SEQ, 256>>>(x, embed, h);
    rms_scale_kernel<<<SEQ, 256>>>(h, rs);
    convAS_kernel<<<cv_h, 256>>>(h, rs, ln1, a4, SEQ, H);

    cudaEventRecord(eFork, 0);
    cudaStreamWaitEvent(s2, eFork, 0);

    convB_qkv_kernel<<<dim3(H / 16, H / 128, 3), 256, 0, s2>>>(Wq, Wk, Wv, wqkv);
    cudaEventRecord(eW[0], s2);
    convB_kernel<<<dim3(H / 16, H / 128), 256, 0, s2>>>(Wo, wo, H, H, 0);
    cudaEventRecord(eW[1], s2);

    cudaStreamWaitEvent(0, eW[0], 0);
    tgemm2_kernel<<<grid_qkv, 256, GSM3>>>(SEQ, 3 * H, KB_H, KB_H / 2, a4,
                                           wqkv, nullptr, nullptr, qkv);

    // remaining weight conversions on s2
    convB_kernel<<<dim3(H / 16, FF / 128), 256, 0, s2>>>(Wg, wgu, H, FF, 0);
    convB_kernel<<<dim3(H / 16, FF / 128), 256, 0, s2>>>(Wu, wgu, H, FF, FF / 8);
    cudaEventRecord(eW[2], s2);
    convB_kernel<<<dim3(FF / 16, H / 128), 256, 0, s2>>>(Wd, wd, FF, H, 0);
    cudaEventRecord(eW[3], s2);
    for (int l = 1; l < NL; l++) {
        convB_qkv_kernel<<<dim3(H / 16, H / 128, 3), 256, 0, s2>>>(
            Wq + (size_t)l * H * H, Wk + (size_t)l * H * H, Wv + (size_t)l * H * H,
            wqkv + l * SQKV4);
        cudaEventRecord(eW[l * 4 + 0], s2);
        convB_kernel<<<dim3(H / 16, H / 128), 256, 0, s2>>>(Wo + (size_t)l * H * H, wo + l * SWQ4, H, H, 0);
        cudaEventRecord(eW[l * 4 + 1], s2);
        uint4* wgu_l = wgu + l * SWGU4;
        convB_kernel<<<dim3(H / 16, FF / 128), 256, 0, s2>>>(Wg + (size_t)l * H * FF, wgu_l, H, FF, 0);
        convB_kernel<<<dim3(H / 16, FF / 128), 256, 0, s2>>>(Wu + (size_t)l * H * FF, wgu_l, H, FF, FF / 8);
        cudaEventRecord(eW[l * 4 + 2], s2);
        convB_kernel<<<dim3(FF / 16, H / 128), 256, 0, s2>>>(Wd + (size_t)l * FF * H, wd + l * SWD4, FF, H, 0);
        cudaEventRecord(eW[l * 4 + 3], s2);
    }
    convB_kernel<<<dim3(H / 16, OUT / 128), 256, 0, s2>>>(Wout, wout, H, OUT, 0);
    cudaEventRecord(eW[NL * 4], s2);

    // ---- main stream: rest of the forward pass ----
    for (int l = 0; l < NL; l++) {
        if (l > 0) {
            rms_scale_kernel<<<SEQ, 256>>>(h, rs);
            convAS_kernel<<<cv_h, 256>>>(h, rs, ln1 + (size_t)l * H, a4, SEQ, H);
            cudaStreamWaitEvent(0, eW[l * 4 + 0], 0);
            tgemm2_kernel<<<grid_qkv, 256, GSM3>>>(SEQ, 3 * H, KB_H, KB_H / 2, a4,
                                                   wqkv + l * SQKV4, nullptr, nullptr, qkv);
        }
        rope_kernel<<<SEQ, 256>>>(qkv, qkv + H, 3 * H);
        attn8_kernel<<<dim3(SEQ / 8, NH), 128>>>(qkv, qkv + H, qkv + 2 * H, ao, 3 * H);
        convA_kernel<<<cv_h, 256>>>(ao, a4, SEQ, H);
        cudaStreamWaitEvent(0, eW[l * 4 + 1], 0);
        tgemm2_kernel<<<grid_h, 256, GSM3>>>(SEQ, H, KB_H, KB_H / 2, a4,
                                             wo + l * SWQ4, h, nullptr, h);

        rms_scale_kernel<<<SEQ, 256>>>(h, rs);
        convAS_kernel<<<cv_h, 256>>>(h, rs, ln2 + (size_t)l * H, a4, SEQ, H);
        cudaStreamWaitEvent(0, eW[l * 4 + 2], 0);
        tgemm2_kernel<<<grid_gu, 256, GSM3>>>(SEQ, 2 * FF, KB_H, KB_H / 2, a4,
                                              wgu + l * SWGU4, nullptr, nullptr, gu);
        siluconv_kernel<<<cv_f, 256>>>(gu, a4, SEQ, FF);
        cudaStreamWaitEvent(0, eW[l * 4 + 3], 0);
        tgemm2_kernel<<<grid_h, 256, GSM3>>>(SEQ, H, KB_F, KB_F / 2, a4,
                                             wd + l * SWD4, h, nullptr, h);
    }

    rms_scale_kernel<<<SEQ, 256>>>(h, rs);
    convAS_kernel<<<cv_h, 256>>>(h, rs, lnf, a4, SEQ, H);
    cudaStreamWaitEvent(0, eW[NL * 4], 0);
    tgemm2_kernel<<<dim3(OUT / 128, SEQ / 128, SPLITK), 256, GSM3>>>(
        SEQ, OUT, KB_H, KB_H / (2 * SPLITK), a4, wout, nullptr, nullptr, part);
    reduceK_kernel<<<SEQ * OUT / 4 / 256, 256>>>(part, bout, out);
}